// round 1
// baseline (speedup 1.0000x reference)
#include <cuda_runtime.h>
#include <cuda_bf16.h>
#include <math.h>

// Problem constants
#define BATCH 16
#define CQ    512
#define HW    2304          // 48*48
#define NH    8
#define HD    64            // CQ/NH
#define SCALE 0.125f        // HD^-0.5

// GEMM tiling for projections: Y(512 x 2304) = W(512x512) @ X(512x2304) + b, per batch
#define PM 512
#define PK 512
#define PN 2304
#define BM 128
#define BN 64
#define BKT 16

// -------- device scratch (no allocs allowed) --------
__device__ float g_Q[(size_t)BATCH * CQ * HW];   // 75.5 MB
__device__ float g_K[(size_t)BATCH * CQ * HW];
__device__ float g_V[(size_t)BATCH * CQ * HW];
__device__ float g_A[(size_t)BATCH * CQ * HW];   // attention output (pre out-proj)
__device__ float g_P[(size_t)BATCH * NH * HD * HD]; // softmax probs, 2 MB

// ---------------------------------------------------------------------------
// Projection GEMM: per batch b (grid.z), Y_b = W @ X_b + bias
// W: (512,512) row-major (o,c). X_b: (512,2304) row-major (c,hw). Y_b likewise.
// 256 threads, 128x64 block tile, 8x4 per-thread microtile, BK=16.
// ---------------------------------------------------------------------------
__global__ __launch_bounds__(256) void proj_gemm(
    const float* __restrict__ W, const float* __restrict__ X,
    const float* __restrict__ bias, float* __restrict__ Y)
{
    const int b  = blockIdx.z;
    const float* Xb = X + (size_t)b * PK * PN;
    float*       Yb = Y + (size_t)b * PM * PN;

    const int m0 = blockIdx.y * BM;
    const int n0 = blockIdx.x * BN;

    __shared__ float Ws[BKT][136];   // [k][m], padded stride 136 (float4-aligned)
    __shared__ float Xs[BKT][BN];    // [k][n]

    const int tid = threadIdx.x;
    const int tm  = tid / 16;        // 0..15 -> rows tm*8 .. tm*8+7
    const int tn  = tid % 16;        // 0..15 -> cols tn*4 .. tn*4+3

    float acc[8][4];
#pragma unroll
    for (int i = 0; i < 8; i++)
#pragma unroll
        for (int j = 0; j < 4; j++) acc[i][j] = 0.f;

    // W-tile load mapping: 128x16 = 512 float4s; thread does idx=tid and tid+256
    const int wrow0 = tid / 4;              // 0..63
    const int wkq   = (tid % 4) * 4;        // 0,4,8,12

    // X-tile load mapping: 16x64 = 256 float4s; one per thread
    const int xk = tid / 16;                // 0..15
    const int xn = (tid % 16) * 4;          // 0..60

    for (int k0 = 0; k0 < PK; k0 += BKT) {
        float4 w0 = *(const float4*)&W[(size_t)(m0 + wrow0)      * PK + k0 + wkq];
        float4 w1 = *(const float4*)&W[(size_t)(m0 + wrow0 + 64) * PK + k0 + wkq];
        float4 xv = *(const float4*)&Xb[(size_t)(k0 + xk) * PN + n0 + xn];

        __syncthreads();
        Ws[wkq + 0][wrow0] = w0.x; Ws[wkq + 1][wrow0] = w0.y;
        Ws[wkq + 2][wrow0] = w0.z; Ws[wkq + 3][wrow0] = w0.w;
        Ws[wkq + 0][wrow0 + 64] = w1.x; Ws[wkq + 1][wrow0 + 64] = w1.y;
        Ws[wkq + 2][wrow0 + 64] = w1.z; Ws[wkq + 3][wrow0 + 64] = w1.w;
        *(float4*)&Xs[xk][xn] = xv;
        __syncthreads();

#pragma unroll
        for (int kk = 0; kk < BKT; kk++) {
            float4 a0 = *(const float4*)&Ws[kk][tm * 8];
            float4 a1 = *(const float4*)&Ws[kk][tm * 8 + 4];
            float4 bx = *(const float4*)&Xs[kk][tn * 4];
            float am[8] = {a0.x, a0.y, a0.z, a0.w, a1.x, a1.y, a1.z, a1.w};
            float bn4[4] = {bx.x, bx.y, bx.z, bx.w};
#pragma unroll
            for (int i = 0; i < 8; i++)
#pragma unroll
                for (int j = 0; j < 4; j++)
                    acc[i][j] = fmaf(am[i], bn4[j], acc[i][j]);
        }
    }

#pragma unroll
    for (int i = 0; i < 8; i++) {
        const int m = m0 + tm * 8 + i;
        const float bb = bias[m];
        float4 o;
        o.x = acc[i][0] + bb; o.y = acc[i][1] + bb;
        o.z = acc[i][2] + bb; o.w = acc[i][3] + bb;
        *(float4*)&Yb[(size_t)m * PN + n0 + tn * 4] = o;
    }
}

// ---------------------------------------------------------------------------
// Attention scores + softmax: one block per (b, head) = 128 blocks.
// S(64x64) = scale * Q_bn(64x2304) @ K_bn(64x2304)^T, softmax rows -> g_P.
// ---------------------------------------------------------------------------
__global__ __launch_bounds__(256) void attn_scores()
{
    const int bn = blockIdx.x;                       // b*8 + n
    const float* Q = g_Q + (size_t)bn * HD * HW;
    const float* K = g_K + (size_t)bn * HD * HW;

    __shared__ float Qs[64][65];
    __shared__ float Ks[64][65];

    const int tid = threadIdx.x;
    const int tm = tid / 16, tn = tid % 16;

    float acc[4][4];
#pragma unroll
    for (int i = 0; i < 4; i++)
#pragma unroll
        for (int j = 0; j < 4; j++) acc[i][j] = 0.f;

    for (int kt = 0; kt < HW / 64; kt++) {
        __syncthreads();
#pragma unroll
        for (int r = 0; r < 4; r++) {
            const int h = r * 16 + tid / 16;
            const int d = (tid % 16) * 4;
            float4 qv = *(const float4*)&Q[(size_t)h * HW + kt * 64 + d];
            float4 kv = *(const float4*)&K[(size_t)h * HW + kt * 64 + d];
            Qs[h][d + 0] = qv.x; Qs[h][d + 1] = qv.y; Qs[h][d + 2] = qv.z; Qs[h][d + 3] = qv.w;
            Ks[h][d + 0] = kv.x; Ks[h][d + 1] = kv.y; Ks[h][d + 2] = kv.z; Ks[h][d + 3] = kv.w;
        }
        __syncthreads();
#pragma unroll 16
        for (int dd = 0; dd < 64; dd++) {
            float qm[4], kn[4];
#pragma unroll
            for (int i = 0; i < 4; i++) qm[i] = Qs[tm * 4 + i][dd];
#pragma unroll
            for (int j = 0; j < 4; j++) kn[j] = Ks[tn * 4 + j][dd];
#pragma unroll
            for (int i = 0; i < 4; i++)
#pragma unroll
                for (int j = 0; j < 4; j++)
                    acc[i][j] = fmaf(qm[i], kn[j], acc[i][j]);
        }
    }

    // write S into Qs (reuse), then softmax rows
    __syncthreads();
#pragma unroll
    for (int i = 0; i < 4; i++)
#pragma unroll
        for (int j = 0; j < 4; j++)
            Qs[tm * 4 + i][tn * 4 + j] = acc[i][j] * SCALE;
    __syncthreads();

    if (tid < 64) {
        float mx = -1e30f;
#pragma unroll 16
        for (int j = 0; j < 64; j++) mx = fmaxf(mx, Qs[tid][j]);
        float sum = 0.f;
#pragma unroll 16
        for (int j = 0; j < 64; j++) {
            float e = __expf(Qs[tid][j] - mx);
            Qs[tid][j] = e;
            sum += e;
        }
        float inv = 1.f / sum;
#pragma unroll 16
        for (int j = 0; j < 64; j++) Qs[tid][j] *= inv;
    }
    __syncthreads();

    float* P = g_P + (size_t)bn * HD * HD;
#pragma unroll
    for (int i = 0; i < 4; i++)
#pragma unroll
        for (int j = 0; j < 4; j++)
            P[(tm * 4 + i) * HD + tn * 4 + j] = Qs[tm * 4 + i][tn * 4 + j];
}

// ---------------------------------------------------------------------------
// Attention apply: out(64 x 2304) = P(64x64) @ V(64x2304). grid (36, 128).
// ---------------------------------------------------------------------------
__global__ __launch_bounds__(256) void attn_av()
{
    const int dt = blockIdx.x;                       // hw tile (64 cols)
    const int bn = blockIdx.y;
    const float* P = g_P + (size_t)bn * HD * HD;
    const float* V = g_V + (size_t)bn * HD * HW;
    float*       O = g_A + (size_t)bn * HD * HW;

    __shared__ float Ps[64][65];
    __shared__ float Vs[64][65];

    const int tid = threadIdx.x;
    const int tm = tid / 16, tn = tid % 16;

#pragma unroll
    for (int r = 0; r < 4; r++) {
        const int h = r * 16 + tid / 16;
        const int d = (tid % 16) * 4;
        float4 pv = *(const float4*)&P[h * HD + d];
        Ps[h][d + 0] = pv.x; Ps[h][d + 1] = pv.y; Ps[h][d + 2] = pv.z; Ps[h][d + 3] = pv.w;
        float4 vv = *(const float4*)&V[(size_t)h * HW + dt * 64 + d];
        Vs[h][d + 0] = vv.x; Vs[h][d + 1] = vv.y; Vs[h][d + 2] = vv.z; Vs[h][d + 3] = vv.w;
    }
    __syncthreads();

    float acc[4][4];
#pragma unroll
    for (int i = 0; i < 4; i++)
#pragma unroll
        for (int j = 0; j < 4; j++) acc[i][j] = 0.f;

#pragma unroll 16
    for (int k = 0; k < 64; k++) {
        float pm[4], vn[4];
#pragma unroll
        for (int i = 0; i < 4; i++) pm[i] = Ps[tm * 4 + i][k];
#pragma unroll
        for (int j = 0; j < 4; j++) vn[j] = Vs[k][tn * 4 + j];
#pragma unroll
        for (int i = 0; i < 4; i++)
#pragma unroll
            for (int j = 0; j < 4; j++)
                acc[i][j] = fmaf(pm[i], vn[j], acc[i][j]);
    }

#pragma unroll
    for (int i = 0; i < 4; i++) {
        float4 o;
        o.x = acc[i][0]; o.y = acc[i][1]; o.z = acc[i][2]; o.w = acc[i][3];
        *(float4*)&O[(size_t)(tm * 4 + i) * HW + dt * 64 + tn * 4] = o;
    }
}

// ---------------------------------------------------------------------------
extern "C" void kernel_launch(void* const* d_in, const int* in_sizes, int n_in,
                              void* d_out, int out_size)
{
    const float* qf = (const float*)d_in[0];
    const float* kf = (const float*)d_in[1];
    const float* vf = (const float*)d_in[2];
    const float* Wq = (const float*)d_in[3];
    const float* bq = (const float*)d_in[4];
    const float* Wk = (const float*)d_in[5];
    const float* bk = (const float*)d_in[6];
    const float* Wv = (const float*)d_in[7];
    const float* bv = (const float*)d_in[8];
    const float* Wo = (const float*)d_in[9];
    const float* bo = (const float*)d_in[10];
    float* out = (float*)d_out;

    float *pQ, *pK, *pV, *pA;
    cudaGetSymbolAddress((void**)&pQ, g_Q);
    cudaGetSymbolAddress((void**)&pK, g_K);
    cudaGetSymbolAddress((void**)&pV, g_V);
    cudaGetSymbolAddress((void**)&pA, g_A);

    dim3 gp(PN / BN, PM / BM, BATCH);   // (36, 4, 16)
    proj_gemm<<<gp, 256>>>(Wq, qf, bq, pQ);
    proj_gemm<<<gp, 256>>>(Wk, kf, bk, pK);
    proj_gemm<<<gp, 256>>>(Wv, vf, bv, pV);

    attn_scores<<<BATCH * NH, 256>>>();
    attn_av<<<dim3(HW / 64, BATCH * NH), 256>>>();

    proj_gemm<<<gp, 256>>>(Wo, pA, bo, out);
}

// round 4
// speedup vs baseline: 1.9239x; 1.9239x over previous
#include <cuda_runtime.h>
#include <cuda_bf16.h>
#include <cstdint>
#include <math.h>

// ---------------- problem constants ----------------
#define BATCH 16
#define CQ    512
#define HW    2304
#define NH    8
#define HD    64
#define SCALE 0.125f
#define KDIM  512
#define NT_PER_B 18                  // 2304/128 n-tiles per batch

// ---------------- device scratch ----------------
__device__ float g_Q[(size_t)BATCH * CQ * HW];
__device__ float g_K[(size_t)BATCH * CQ * HW];
__device__ float g_V[(size_t)BATCH * CQ * HW];
__device__ float g_A[(size_t)BATCH * CQ * HW];
__device__ float g_P[(size_t)BATCH * NH * HD * HD];
__device__ float g_Sp[(size_t)BATCH * NH * 6 * HD * HD];   // split-K partial scores
__device__ __nv_bfloat16 g_Whi[4][(size_t)KDIM * KDIM];
__device__ __nv_bfloat16 g_Wlo[4][(size_t)KDIM * KDIM];

// ---------------- helpers ----------------
__device__ __forceinline__ uint32_t smem_u32(const void* p) {
    uint32_t a;
    asm("{ .reg .u64 t; cvta.to.shared.u64 t, %1; cvt.u32.u64 %0, t; }" : "=r"(a) : "l"(p));
    return a;
}
__device__ __forceinline__ void cp16(uint32_t dst, const void* src) {
    asm volatile("cp.async.cg.shared.global [%0], [%1], 16;" :: "r"(dst), "l"(src));
}
__device__ __forceinline__ void cp_commit() { asm volatile("cp.async.commit_group;"); }
__device__ __forceinline__ void cp_wait1()  { asm volatile("cp.async.wait_group 1;"); }
__device__ __forceinline__ void cp_wait0()  { asm volatile("cp.async.wait_group 0;"); }

__device__ __forceinline__ void ldsm4(uint32_t* r, uint32_t addr) {
    asm volatile("ldmatrix.sync.aligned.m8n8.x4.shared.b16 {%0,%1,%2,%3}, [%4];"
        : "=r"(r[0]), "=r"(r[1]), "=r"(r[2]), "=r"(r[3]) : "r"(addr));
}
__device__ __forceinline__ void ldsm4t(uint32_t* r, uint32_t addr) {
    asm volatile("ldmatrix.sync.aligned.m8n8.x4.trans.shared.b16 {%0,%1,%2,%3}, [%4];"
        : "=r"(r[0]), "=r"(r[1]), "=r"(r[2]), "=r"(r[3]) : "r"(addr));
}
__device__ __forceinline__ void mma16816(float* c, const uint32_t* a, const uint32_t* b) {
    asm volatile(
        "mma.sync.aligned.m16n8k16.row.col.f32.bf16.bf16.f32 "
        "{%0,%1,%2,%3}, {%4,%5,%6,%7}, {%8,%9}, {%0,%1,%2,%3};"
        : "+f"(c[0]), "+f"(c[1]), "+f"(c[2]), "+f"(c[3])
        : "r"(a[0]), "r"(a[1]), "r"(a[2]), "r"(a[3]), "r"(b[0]), "r"(b[1]));
}
__device__ __forceinline__ uint32_t pack_bf16(__nv_bfloat16 a, __nv_bfloat16 b) {
    return (uint32_t)__bfloat16_as_ushort(a) | ((uint32_t)__bfloat16_as_ushort(b) << 16);
}
__device__ __forceinline__ void split2(float x, float y, uint32_t& h, uint32_t& l) {
    __nv_bfloat16 hx = __float2bfloat16(x), hy = __float2bfloat16(y);
    __nv_bfloat16 lx = __float2bfloat16(x - __bfloat162float(hx));
    __nv_bfloat16 ly = __float2bfloat16(y - __bfloat162float(hy));
    h = pack_bf16(hx, hy);
    l = pack_bf16(lx, ly);
}

// ---------------- weight split ----------------
__global__ __launch_bounds__(256) void convert_w(
    const float* __restrict__ w0, const float* __restrict__ w1,
    const float* __restrict__ w2, const float* __restrict__ w3,
    __nv_bfloat16* __restrict__ hi, __nv_bfloat16* __restrict__ lo)
{
    int g = blockIdx.x * 256 + threadIdx.x;     // 262144 float4s across 4 weights
    int w = g >> 16;
    int rem = g & 65535;
    const float* W = (w == 0) ? w0 : (w == 1) ? w1 : (w == 2) ? w2 : w3;
    float4 v = ((const float4*)W)[rem];
    uint32_t h01, l01, h23, l23;
    split2(v.x, v.y, h01, l01);
    split2(v.z, v.w, h23, l23);
    size_t o = ((size_t)w * KDIM * KDIM + (size_t)rem * 4) / 2;   // in uint32 units
    ((uint32_t*)hi)[o + 0] = h01; ((uint32_t*)hi)[o + 1] = h23;
    ((uint32_t*)lo)[o + 0] = l01; ((uint32_t*)lo)[o + 1] = l23;
}

// ---------------- bf16x3 GEMM via mma.sync ----------------
// Y[b][m][hw] = sum_k W[m][k] * X[b][k][hw] + bias[m]
// Grid (4, 288): blockIdx.x = m-tile (128), blockIdx.y = n-tile (128 over b*hw).
#define AS_STRIDE 80                  // A row bytes: 32 k * 2B + 16 pad
#define BS_STRIDE 272                 // B row bytes: 128 n * 2B + 16 pad
#define A_PLANE (128 * AS_STRIDE)     // 10240
#define B_PLANE (32 * BS_STRIDE)      // 8704
#define A_STAGE (2 * A_PLANE)         // hi+lo
#define B_STAGE (2 * B_PLANE)
#define OFF_B   (2 * A_STAGE)
#define GEMM_SMEM (OFF_B + 2 * B_STAGE)   // 75776 B

__global__ __launch_bounds__(256) void gemm_bf16x3(
    const __nv_bfloat16* __restrict__ Whi, const __nv_bfloat16* __restrict__ Wlo,
    const float* __restrict__ X, const float* __restrict__ bias,
    float* __restrict__ Y)
{
    extern __shared__ char smem[];
    const uint32_t sb = smem_u32(smem);
    const int tid = threadIdx.x;
    const int l = tid & 31, wid = tid >> 5;
    const int wm = wid >> 2, wn = wid & 3;

    const int m0 = blockIdx.x * 128;
    const int b  = blockIdx.y / NT_PER_B;
    const int hw0 = (blockIdx.y % NT_PER_B) * 128;
    const float* Xb = X + (size_t)b * KDIM * HW + hw0;

    // ---- producers ----
    const int brow = tid >> 3;            // 0..31
    const int bc   = tid & 7;

    float4 rB[4];

#define LOAD_A(s)                                                              \
    {                                                                          \
        const int k0_ = (s) * 32;                                              \
        uint32_t abase_ = sb + ((s) & 1) * A_STAGE;                            \
        _Pragma("unroll")                                                      \
        for (int it = 0; it < 4; it++) {                                       \
            int c = tid + it * 256;                                            \
            int plane = c >> 9;                                                \
            int cc = c & 511;                                                  \
            int m = cc >> 2, ch = cc & 3;                                      \
            const __nv_bfloat16* src = (plane ? Wlo : Whi) +                   \
                (size_t)(m0 + m) * KDIM + k0_ + ch * 8;                        \
            cp16(abase_ + plane * A_PLANE + m * AS_STRIDE + ch * 16, src);     \
        }                                                                      \
        cp_commit();                                                           \
    }

#define LDG_B(s)                                                               \
    {                                                                          \
        const int k0_ = (s) * 32;                                              \
        _Pragma("unroll")                                                      \
        for (int it = 0; it < 4; it++) {                                       \
            int c4 = bc + it * 8;                                              \
            rB[it] = *(const float4*)(Xb + (size_t)(k0_ + brow) * HW + c4 * 4);\
        }                                                                      \
    }

#define STS_B(buf)                                                             \
    {                                                                          \
        uint32_t bb_ = sb + OFF_B + (buf) * B_STAGE + brow * BS_STRIDE;        \
        _Pragma("unroll")                                                      \
        for (int it = 0; it < 4; it++) {                                       \
            int c4 = bc + it * 8;                                              \
            uint32_t h0, l0, h1, l1;                                           \
            split2(rB[it].x, rB[it].y, h0, l0);                                \
            split2(rB[it].z, rB[it].w, h1, l1);                                \
            uint32_t d_ = bb_ + c4 * 8;                                        \
            asm volatile("st.shared.v2.b32 [%0], {%1,%2};" :: "r"(d_), "r"(h0), "r"(h1)); \
            asm volatile("st.shared.v2.b32 [%0], {%1,%2};" :: "r"(d_ + B_PLANE), "r"(l0), "r"(l1)); \
        }                                                                      \
    }

    float acc[4][4][4];
#pragma unroll
    for (int i = 0; i < 4; i++)
#pragma unroll
        for (int j = 0; j < 4; j++)
#pragma unroll
            for (int q = 0; q < 4; q++) acc[i][j][q] = 0.f;

    const uint32_t aFragBase = (wm * 64 + (l & 15)) * AS_STRIDE + (l >> 4) * 16;
    const uint32_t bFragBase = (l & 15) * BS_STRIDE + wn * 64 + (l >> 4) * 16;

#define COMPUTE(buf)                                                           \
    {                                                                          \
        uint32_t aB_ = sb + (buf) * A_STAGE + aFragBase;                       \
        uint32_t bB_ = sb + OFF_B + (buf) * B_STAGE + bFragBase;               \
        _Pragma("unroll")                                                      \
        for (int kh = 0; kh < 2; kh++) {                                       \
            uint32_t Ahi[4][4], Alo[4][4], Bh[2][4], Bl[2][4];                 \
            uint32_t ao = aB_ + kh * 32;                                       \
            uint32_t bo = bB_ + kh * 16 * BS_STRIDE;                           \
            _Pragma("unroll")                                                  \
            for (int p = 0; p < 2; p++) ldsm4t(Bh[p], bo + p * 32);            \
            _Pragma("unroll")                                                  \
            for (int p = 0; p < 2; p++) ldsm4t(Bl[p], bo + B_PLANE + p * 32);  \
            _Pragma("unroll")                                                  \
            for (int i = 0; i < 4; i++) ldsm4(Ahi[i], ao + i * 16 * AS_STRIDE);\
            _Pragma("unroll")                                                  \
            for (int i = 0; i < 4; i++) ldsm4(Alo[i], ao + A_PLANE + i * 16 * AS_STRIDE); \
            _Pragma("unroll")                                                  \
            for (int i = 0; i < 4; i++) {                                      \
                _Pragma("unroll")                                              \
                for (int j = 0; j < 4; j++) {                                  \
                    uint32_t bh[2] = {Bh[j >> 1][(j & 1) * 2], Bh[j >> 1][(j & 1) * 2 + 1]}; \
                    uint32_t bl[2] = {Bl[j >> 1][(j & 1) * 2], Bl[j >> 1][(j & 1) * 2 + 1]}; \
                    mma16816(acc[i][j], Ahi[i], bh);                           \
                    mma16816(acc[i][j], Ahi[i], bl);                           \
                    mma16816(acc[i][j], Alo[i], bh);                           \
                }                                                              \
            }                                                                  \
        }                                                                      \
    }

    // ---- prologue ----
    LOAD_A(0);           // group G0 -> A buf 0
    LOAD_A(1);           // group G1 -> A buf 1
    LDG_B(0);
    STS_B(0);
    LDG_B(1);            // stage-1 B staged in registers
    cp_wait1();          // G0 complete
    __syncthreads();     // A0 + B0 visible to all warps

    // ---- mainloop: 16 k-stages of 32 ----
    // Hazard-free ordering: prefetches that overwrite stage-s buffers are
    // issued only AFTER the post-COMPUTE barrier (all warps done reading).
#pragma unroll 1
    for (int s = 0; s < 16; s++) {
        const int buf = s & 1;
        COMPUTE(buf);
        __syncthreads();                  // all warps done with stage-s buffers
        if (s + 1 < 16) {
            STS_B(buf ^ 1);               // B for stage s+1 (rB holds it)
            if (s + 2 < 16) {
                LDG_B(s + 2);             // refill rB for stage s+2
                LOAD_A(s + 2);            // cp.async into A buf (now idle)
                cp_wait1();               // G(s+1) complete
            } else {
                cp_wait0();               // only G(s+1) left
            }
            __syncthreads();              // STS_B visible + A(s+1) ready
        }
    }

    // ---- epilogue ----
    const size_t ybase = ((size_t)b * CQ + m0 + wm * 64) * HW + hw0 + wn * 32;
#pragma unroll
    for (int i = 0; i < 4; i++) {
        const int r0 = i * 16 + (l >> 2);
        const float b0 = bias[m0 + wm * 64 + r0];
        const float b1 = bias[m0 + wm * 64 + r0 + 8];
#pragma unroll
        for (int j = 0; j < 4; j++) {
            const int cc = j * 8 + (l & 3) * 2;
            float2 v0 = make_float2(acc[i][j][0] + b0, acc[i][j][1] + b0);
            float2 v1 = make_float2(acc[i][j][2] + b1, acc[i][j][3] + b1);
            *(float2*)&Y[ybase + (size_t)r0 * HW + cc] = v0;
            *(float2*)&Y[ybase + (size_t)(r0 + 8) * HW + cc] = v1;
        }
    }
}

// ---------------- attention: split-K partial scores ----------------
__global__ __launch_bounds__(256) void attn_scores_part()
{
    const int ks = blockIdx.x;                      // 0..5
    const int bn = blockIdx.y;                      // 0..127
    const float* Q = g_Q + (size_t)bn * HD * HW;
    const float* K = g_K + (size_t)bn * HD * HW;

    __shared__ float Qs[64][65];
    __shared__ float Ks[64][65];

    const int tid = threadIdx.x;
    const int tm = tid / 16, tn = tid % 16;

    float acc[4][4];
#pragma unroll
    for (int i = 0; i < 4; i++)
#pragma unroll
        for (int j = 0; j < 4; j++) acc[i][j] = 0.f;

    for (int kt = ks * 6; kt < ks * 6 + 6; kt++) {
        __syncthreads();
#pragma unroll
        for (int r = 0; r < 4; r++) {
            const int h = r * 16 + tid / 16;
            const int d = (tid % 16) * 4;
            float4 qv = *(const float4*)&Q[(size_t)h * HW + kt * 64 + d];
            float4 kv = *(const float4*)&K[(size_t)h * HW + kt * 64 + d];
            Qs[h][d + 0] = qv.x; Qs[h][d + 1] = qv.y; Qs[h][d + 2] = qv.z; Qs[h][d + 3] = qv.w;
            Ks[h][d + 0] = kv.x; Ks[h][d + 1] = kv.y; Ks[h][d + 2] = kv.z; Ks[h][d + 3] = kv.w;
        }
        __syncthreads();
#pragma unroll 16
        for (int dd = 0; dd < 64; dd++) {
            float qm[4], kn[4];
#pragma unroll
            for (int i = 0; i < 4; i++) qm[i] = Qs[tm * 4 + i][dd];
#pragma unroll
            for (int j = 0; j < 4; j++) kn[j] = Ks[tn * 4 + j][dd];
#pragma unroll
            for (int i = 0; i < 4; i++)
#pragma unroll
                for (int j = 0; j < 4; j++)
                    acc[i][j] = fmaf(qm[i], kn[j], acc[i][j]);
        }
    }

    float* Sp = g_Sp + ((size_t)bn * 6 + ks) * HD * HD;
#pragma unroll
    for (int i = 0; i < 4; i++)
#pragma unroll
        for (int j = 0; j < 4; j++)
            Sp[(tm * 4 + i) * HD + tn * 4 + j] = acc[i][j];
}

// ---------------- attention: reduce + softmax ----------------
__global__ __launch_bounds__(256) void attn_softmax()
{
    const int bn = blockIdx.x;
    __shared__ float S[64][65];
    const float* base = g_Sp + (size_t)bn * 6 * HD * HD;
    const int tid = threadIdx.x;

    for (int e = tid; e < 4096; e += 256) {
        float s = 0.f;
#pragma unroll
        for (int ks = 0; ks < 6; ks++) s += base[ks * 4096 + e];
        S[e >> 6][e & 63] = s * SCALE;
    }
    __syncthreads();

    if (tid < 64) {
        float mx = -1e30f;
#pragma unroll 16
        for (int j = 0; j < 64; j++) mx = fmaxf(mx, S[tid][j]);
        float sum = 0.f;
#pragma unroll 16
        for (int j = 0; j < 64; j++) {
            float e = __expf(S[tid][j] - mx);
            S[tid][j] = e;
            sum += e;
        }
        float inv = 1.f / sum;
#pragma unroll 16
        for (int j = 0; j < 64; j++) S[tid][j] *= inv;
    }
    __syncthreads();

    float* P = g_P + (size_t)bn * HD * HD;
    for (int e = tid; e < 4096; e += 256)
        P[e] = S[e >> 6][e & 63];
}

// ---------------- attention: P @ V ----------------
__global__ __launch_bounds__(256) void attn_av()
{
    const int dt = blockIdx.x;
    const int bn = blockIdx.y;
    const float* P = g_P + (size_t)bn * HD * HD;
    const float* V = g_V + (size_t)bn * HD * HW;
    float*       O = g_A + (size_t)bn * HD * HW;

    __shared__ float Ps[64][65];
    __shared__ float Vs[64][65];

    const int tid = threadIdx.x;
    const int tm = tid / 16, tn = tid % 16;

#pragma unroll
    for (int r = 0; r < 4; r++) {
        const int h = r * 16 + tid / 16;
        const int d = (tid % 16) * 4;
        float4 pv = *(const float4*)&P[h * HD + d];
        Ps[h][d + 0] = pv.x; Ps[h][d + 1] = pv.y; Ps[h][d + 2] = pv.z; Ps[h][d + 3] = pv.w;
        float4 vv = *(const float4*)&V[(size_t)h * HW + dt * 64 + d];
        Vs[h][d + 0] = vv.x; Vs[h][d + 1] = vv.y; Vs[h][d + 2] = vv.z; Vs[h][d + 3] = vv.w;
    }
    __syncthreads();

    float acc[4][4];
#pragma unroll
    for (int i = 0; i < 4; i++)
#pragma unroll
        for (int j = 0; j < 4; j++) acc[i][j] = 0.f;

#pragma unroll 16
    for (int k = 0; k < 64; k++) {
        float pm[4], vn[4];
#pragma unroll
        for (int i = 0; i < 4; i++) pm[i] = Ps[tm * 4 + i][k];
#pragma unroll
        for (int j = 0; j < 4; j++) vn[j] = Vs[k][tn * 4 + j];
#pragma unroll
        for (int i = 0; i < 4; i++)
#pragma unroll
            for (int j = 0; j < 4; j++)
                acc[i][j] = fmaf(pm[i], vn[j], acc[i][j]);
    }

#pragma unroll
    for (int i = 0; i < 4; i++) {
        float4 o;
        o.x = acc[i][0]; o.y = acc[i][1]; o.z = acc[i][2]; o.w = acc[i][3];
        *(float4*)&O[(size_t)(tm * 4 + i) * HW + dt * 64 + tn * 4] = o;
    }
}

// ---------------------------------------------------------------------------
extern "C" void kernel_launch(void* const* d_in, const int* in_sizes, int n_in,
                              void* d_out, int out_size)
{
    const float* qf = (const float*)d_in[0];
    const float* kf = (const float*)d_in[1];
    const float* vf = (const float*)d_in[2];
    const float* Wq = (const float*)d_in[3];
    const float* bq = (const float*)d_in[4];
    const float* Wk = (const float*)d_in[5];
    const float* bk = (const float*)d_in[6];
    const float* Wv = (const float*)d_in[7];
    const float* bv = (const float*)d_in[8];
    const float* Wo = (const float*)d_in[9];
    const float* bo = (const float*)d_in[10];
    float* out = (float*)d_out;

    float *pQ, *pK, *pV, *pA;
    cudaGetSymbolAddress((void**)&pQ, g_Q);
    cudaGetSymbolAddress((void**)&pK, g_K);
    cudaGetSymbolAddress((void**)&pV, g_V);
    cudaGetSymbolAddress((void**)&pA, g_A);
    __nv_bfloat16 *whi, *wlo;
    cudaGetSymbolAddress((void**)&whi, g_Whi);
    cudaGetSymbolAddress((void**)&wlo, g_Wlo);
    const size_t WSZ = (size_t)KDIM * KDIM;

    static int smem_set = 0;
    if (!smem_set) {
        cudaFuncSetAttribute(gemm_bf16x3, cudaFuncAttributeMaxDynamicSharedMemorySize, GEMM_SMEM);
        smem_set = 1;
    }

    convert_w<<<1024, 256>>>(Wq, Wk, Wv, Wo, whi, wlo);

    dim3 gg(4, 288);
    gemm_bf16x3<<<gg, 256, GEMM_SMEM>>>(whi + 0 * WSZ, wlo + 0 * WSZ, qf, bq, pQ);
    gemm_bf16x3<<<gg, 256, GEMM_SMEM>>>(whi + 1 * WSZ, wlo + 1 * WSZ, kf, bk, pK);
    gemm_bf16x3<<<gg, 256, GEMM_SMEM>>>(whi + 2 * WSZ, wlo + 2 * WSZ, vf, bv, pV);

    attn_scores_part<<<dim3(6, BATCH * NH), 256>>>();
    attn_softmax<<<BATCH * NH, 256>>>();
    attn_av<<<dim3(HW / 64, BATCH * NH), 256>>>();

    gemm_bf16x3<<<gg, 256, GEMM_SMEM>>>(whi + 3 * WSZ, wlo + 3 * WSZ, pA, bo, out);
}